// round 15
// baseline (speedup 1.0000x reference)
#include <cuda_runtime.h>
#include <cuda_bf16.h>
#include <cstdint>

#define NN    30000
#define NE    600000
#define C_IN  256
#define C_HID 128
#define C_OUT 64

// ---------------- scratch (device globals — no allocation allowed) ----------
__device__ int   g_deg[NN];
__device__ float g_dinv[NN];
__device__ int   g_rowptr[NN + 1];
__device__ int   g_cursor[NN];
__device__ int   g_col[NE];
__device__ int   g_is64;
__device__ float g_hs1[(size_t)NN * C_HID];   // dinv * (X @ W1)
__device__ float g_hs2[(size_t)NN * C_OUT];   // dinv * (h2 @ W2)
// bf16 split operands for tensor-core GEMMs
__device__ __nv_bfloat16 g_xhi [(size_t)NN * C_IN];
__device__ __nv_bfloat16 g_xlo [(size_t)NN * C_IN];
__device__ __nv_bfloat16 g_h2hi[(size_t)NN * C_HID];
__device__ __nv_bfloat16 g_h2lo[(size_t)NN * C_HID];
__device__ __nv_bfloat16 g_w1thi[C_HID * C_IN];   // W1^T [n][k]
__device__ __nv_bfloat16 g_w1tlo[C_HID * C_IN];
__device__ __nv_bfloat16 g_w2thi[C_OUT * C_HID];  // W2^T [n][k]
__device__ __nv_bfloat16 g_w2tlo[C_OUT * C_HID];

// ---------------- init: zero degrees + edge dtype detection (fused) ---------
__global__ void init_kernel(const long long* __restrict__ p) {
    int i = blockIdx.x * blockDim.x + threadIdx.x;
    if (i < NN) g_deg[i] = 0;
    if (i == 0) {
        int ok = 1;
        for (int e = 0; e < 64; e++) {
            long long v = p[e];
            if (v < 0 || v >= NN) { ok = 0; break; }
        }
        g_is64 = ok;
    }
}

__global__ void count_deg_kernel(const void* __restrict__ ei) {
    int e = blockIdx.x * blockDim.x + threadIdx.x;
    if (e >= NE) return;
    int d;
    if (g_is64) d = (int)((const long long*)ei)[NE + e];
    else        d = ((const int*)ei)[NE + e];
    atomicAdd(&g_deg[d], 1);
}

// ---------------- single-pass scan: 1024 threads x 30 items in registers ----
// Replaces the 30-chunk sequential scan (was 30.5us of grid=1 serialization).
__global__ __launch_bounds__(1024)
void scan_dinv_kernel() {
    constexpr int ITEMS = 30;                 // 1024*30 = 30720 >= NN
    __shared__ int warp_sums[32];
    const int tid = threadIdx.x, lane = tid & 31, wid = tid >> 5;
    const int base = tid * ITEMS;

    int v[ITEMS];
    int sum = 0;
    #pragma unroll
    for (int j = 0; j < ITEMS; j++) {
        int i = base + j;
        v[j] = (i < NN) ? g_deg[i] : 0;
        sum += v[j];
    }
    // inclusive warp scan of per-thread sums
    int s = sum;
    #pragma unroll
    for (int o = 1; o < 32; o <<= 1) {
        int t = __shfl_up_sync(0xffffffffu, s, o);
        if (lane >= o) s += t;
    }
    if (lane == 31) warp_sums[wid] = s;
    __syncthreads();
    if (wid == 0) {
        int ws = warp_sums[lane];
        #pragma unroll
        for (int o = 1; o < 32; o <<= 1) {
            int t = __shfl_up_sync(0xffffffffu, ws, o);
            if (lane >= o) ws += t;
        }
        warp_sums[lane] = ws;
    }
    __syncthreads();
    int run = ((wid == 0) ? 0 : warp_sums[wid - 1]) + s - sum;  // thread-exclusive

    #pragma unroll
    for (int j = 0; j < ITEMS; j++) {
        int i = base + j;
        if (i < NN) {
            g_rowptr[i] = run;
            g_cursor[i] = run;
            g_dinv[i]   = rsqrtf((float)(v[j] + 1));   // +1 self loop
        }
        run += v[j];
    }
    if (tid == 1023) g_rowptr[NN] = run;               // global total
}

__global__ void scatter_kernel(const void* __restrict__ ei) {
    int e = blockIdx.x * blockDim.x + threadIdx.x;
    if (e >= NE) return;
    int s, d;
    if (g_is64) {
        s = (int)((const long long*)ei)[e];
        d = (int)((const long long*)ei)[NE + e];
    } else {
        s = ((const int*)ei)[e];
        d = ((const int*)ei)[NE + e];
    }
    int pos = atomicAdd(&g_cursor[d], 1);
    g_col[pos] = s;
}

// ---------------- bf16 split prep (x + both weights in one kernel) ----------
__device__ __forceinline__ void split_bf16(float v, __nv_bfloat16& hi,
                                           __nv_bfloat16& lo) {
    hi = __float2bfloat16(v);
    lo = __float2bfloat16(v - __bfloat162float(hi));
}

#define NX4   (NN * C_IN / 4)                     // 1,920,000 float4s of x
#define NW1   (C_HID * C_IN)
#define NW2   (C_OUT * C_HID)

__global__ void prep_kernel(const float* __restrict__ x,
                            const float* __restrict__ W1,
                            const float* __restrict__ W2) {
    int i = blockIdx.x * blockDim.x + threadIdx.x;
    if (i < NX4) {
        float4 v = ((const float4*)x)[i];
        __nv_bfloat16 h[4], l[4];
        split_bf16(v.x, h[0], l[0]); split_bf16(v.y, h[1], l[1]);
        split_bf16(v.z, h[2], l[2]); split_bf16(v.w, h[3], l[3]);
        *(uint2*)&g_xhi[(size_t)i * 4] = *(uint2*)h;
        *(uint2*)&g_xlo[(size_t)i * 4] = *(uint2*)l;
    } else {
        int j = i - NX4;
        if (j < NW1) {                         // W1^T[n][k] = W1[k][n]
            int n = j / C_IN, k = j % C_IN;
            split_bf16(W1[(size_t)k * C_HID + n], g_w1thi[j], g_w1tlo[j]);
        } else if (j < NW1 + NW2) {            // W2^T[n][k] = W2[k][n]
            int q = j - NW1;
            int n = q / C_HID, k = q % C_HID;
            split_bf16(W2[(size_t)k * C_OUT + n], g_w2thi[q], g_w2tlo[q]);
        }
    }
}

// ---------------- mma.sync helpers (baseline PTX — no sm_103a features) -----
__device__ __forceinline__ void ldm_x4(uint32_t& r0, uint32_t& r1,
                                       uint32_t& r2, uint32_t& r3,
                                       uint32_t addr) {
    asm volatile("ldmatrix.sync.aligned.m8n8.x4.shared.b16 {%0,%1,%2,%3}, [%4];"
                 : "=r"(r0), "=r"(r1), "=r"(r2), "=r"(r3) : "r"(addr));
}
__device__ __forceinline__ void mma_bf16(float* c, const uint32_t* a,
                                         const uint32_t* b) {
    asm volatile(
        "mma.sync.aligned.m16n8k16.row.col.f32.bf16.bf16.f32 "
        "{%0,%1,%2,%3}, {%4,%5,%6,%7}, {%8,%9}, {%0,%1,%2,%3};"
        : "+f"(c[0]), "+f"(c[1]), "+f"(c[2]), "+f"(c[3])
        : "r"(a[0]), "r"(a[1]), "r"(a[2]), "r"(a[3]), "r"(b[0]), "r"(b[1]));
}
__device__ __forceinline__ uint32_t smem_u32(const void* p) {
    uint32_t a;
    asm("{ .reg .u64 t; cvta.to.shared.u64 t, %1; cvt.u32.u64 %0, t; }"
        : "=r"(a) : "l"(p));
    return a;
}

// ---------------- tensor-core GEMM (HMMA) with fused dinv scale -------------
// out[row, n] = dinv[row] * sum_k A[row,k] * WT[n,k]
// 3-term bf16 split: AhiBhi + AloBhi + AhiBlo, fp32 accumulate.
// BM=128, BN = full N, BK=32, 256 threads = 8 warps (4 M x 2 N).
template<int BN, int K_TOT, int LAYER>
__global__ __launch_bounds__(256)
void gemm_mma_kernel() {
    constexpr int BM = 128, BK = 32;
    constexpr int STRIDE = BK + 8;              // bf16 units; 80B rows (conflict-free)
    constexpr int WN = BN / 2;                  // warp n-extent (64 / 32)
    constexpr int NFRAG = WN / 8;               // 8 / 4
    constexpr int MFRAG = 2;                    // 32 rows per warp

    const __nv_bfloat16 *Ahi, *Alo, *Bhi, *Blo;
    float* out;
    if constexpr (LAYER == 1) {
        Ahi = g_xhi;  Alo = g_xlo;  Bhi = g_w1thi; Blo = g_w1tlo; out = g_hs1;
    } else {
        Ahi = g_h2hi; Alo = g_h2lo; Bhi = g_w2thi; Blo = g_w2tlo; out = g_hs2;
    }

    __shared__ __nv_bfloat16 sAh[BM * STRIDE], sAl[BM * STRIDE];
    __shared__ __nv_bfloat16 sBh[BN * STRIDE], sBl[BN * STRIDE];

    const int tid   = threadIdx.x;
    const int wid   = tid >> 5, lane = tid & 31;
    const int warp_m = wid & 3, warp_n = wid >> 2;
    const int bRow  = blockIdx.x * BM;

    const uint32_t uAh = smem_u32(sAh), uAl = smem_u32(sAl);
    const uint32_t uBh = smem_u32(sBh), uBl = smem_u32(sBl);

    float acc[MFRAG][NFRAG][4];
    #pragma unroll
    for (int f = 0; f < MFRAG; f++)
        #pragma unroll
        for (int n = 0; n < NFRAG; n++)
            #pragma unroll
            for (int c = 0; c < 4; c++) acc[f][n][c] = 0.f;

    // ldmatrix per-lane row/col (same pattern for A[M][K] and B[N][K])
    const int lrow = lane & 15;
    const int lcol = (lane >> 4) << 3;

    for (int k0 = 0; k0 < K_TOT; k0 += BK) {
        // A slabs: BM x BK, vectorized uint4 (8 bf16)
        #pragma unroll
        for (int t = 0; t < BM * BK / 8 / 256; t++) {
            int u = t * 256 + tid;
            int r = u >> 2, c = u & 3;                  // 4 uint4 per row
            int grow = bRow + r;
            uint4 vh = make_uint4(0, 0, 0, 0), vl = make_uint4(0, 0, 0, 0);
            if (grow < NN) {
                size_t src = (size_t)grow * K_TOT + k0 + c * 8;
                vh = *(const uint4*)&Ahi[src];
                vl = *(const uint4*)&Alo[src];
            }
            *(uint4*)&sAh[r * STRIDE + c * 8] = vh;
            *(uint4*)&sAl[r * STRIDE + c * 8] = vl;
        }
        // B slabs: BN x BK
        #pragma unroll
        for (int t = 0; t < (BN * BK / 8 + 255) / 256; t++) {
            int u = t * 256 + tid;
            if (u < BN * BK / 8) {
                int r = u >> 2, c = u & 3;
                size_t src = (size_t)r * K_TOT + k0 + c * 8;
                *(uint4*)&sBh[r * STRIDE + c * 8] = *(const uint4*)&Bhi[src];
                *(uint4*)&sBl[r * STRIDE + c * 8] = *(const uint4*)&Blo[src];
            }
        }
        __syncthreads();

        #pragma unroll
        for (int kk = 0; kk < BK; kk += 16) {
            uint32_t ah[MFRAG][4], al[MFRAG][4];
            #pragma unroll
            for (int f = 0; f < MFRAG; f++) {
                uint32_t off = (uint32_t)((warp_m * 32 + f * 16 + lrow) * STRIDE
                                          + kk + lcol) * 2;
                ldm_x4(ah[f][0], ah[f][1], ah[f][2], ah[f][3], uAh + off);
                ldm_x4(al[f][0], al[f][1], al[f][2], al[f][3], uAl + off);
            }
            uint32_t bh[NFRAG][2], bl[NFRAG][2];
            #pragma unroll
            for (int g = 0; g < NFRAG / 2; g++) {
                uint32_t off = (uint32_t)((warp_n * WN + g * 16 + lrow) * STRIDE
                                          + kk + lcol) * 2;
                uint32_t r0, r1, r2, r3;
                ldm_x4(r0, r1, r2, r3, uBh + off);
                bh[2*g][0] = r0; bh[2*g][1] = r2;
                bh[2*g+1][0] = r1; bh[2*g+1][1] = r3;
                ldm_x4(r0, r1, r2, r3, uBl + off);
                bl[2*g][0] = r0; bl[2*g][1] = r2;
                bl[2*g+1][0] = r1; bl[2*g+1][1] = r3;
            }
            #pragma unroll
            for (int f = 0; f < MFRAG; f++)
                #pragma unroll
                for (int n = 0; n < NFRAG; n++) {
                    mma_bf16(acc[f][n], ah[f], bh[n]);   // hi*hi
                    mma_bf16(acc[f][n], al[f], bh[n]);   // lo*hi
                    mma_bf16(acc[f][n], ah[f], bl[n]);   // hi*lo
                }
        }
        __syncthreads();
    }

    // epilogue: D frag -> lane holds rows (q, q+8), cols 2*(lane%4)+{0,1}
    const int q  = lane >> 2;
    const int cc = (lane & 3) * 2;
    #pragma unroll
    for (int f = 0; f < MFRAG; f++) {
        int r0 = bRow + warp_m * 32 + f * 16 + q;
        int r1 = r0 + 8;
        float s0 = (r0 < NN) ? g_dinv[r0] : 0.f;
        float s1 = (r1 < NN) ? g_dinv[r1] : 0.f;
        #pragma unroll
        for (int n = 0; n < NFRAG; n++) {
            int col = warp_n * WN + n * 8 + cc;
            if (r0 < NN)
                *(float2*)&out[(size_t)r0 * BN + col] =
                    make_float2(acc[f][n][0] * s0, acc[f][n][1] * s0);
            if (r1 < NN)
                *(float2*)&out[(size_t)r1 * BN + col] =
                    make_float2(acc[f][n][2] * s1, acc[f][n][3] * s1);
        }
    }
}

// ---------------- CSR aggregation: one warp per node, MLP-4 unrolled --------
// layer 1: h2 = relu(dinv*(hs1[i] + sum_nbr) + b1), emitted as bf16 hi/lo split
__global__ void aggregate1_kernel(const float* __restrict__ bias) {
    int gw = (blockIdx.x * blockDim.x + threadIdx.x) >> 5;
    if (gw >= NN) return;
    int lane = threadIdx.x & 31;
    int off  = lane * 4;

    float acc[4];
    {
        float4 t = *(const float4*)&g_hs1[(size_t)gw * C_HID + off];
        acc[0] = t.x; acc[1] = t.y; acc[2] = t.z; acc[3] = t.w;
    }
    int s = g_rowptr[gw], e = g_rowptr[gw + 1];
    int i = s;
    for (; i + 4 <= e; i += 4) {               // MLP-4: batch cols, then rows
        int c0 = g_col[i], c1 = g_col[i + 1], c2 = g_col[i + 2], c3 = g_col[i + 3];
        float4 t0 = *(const float4*)&g_hs1[(size_t)c0 * C_HID + off];
        float4 t1 = *(const float4*)&g_hs1[(size_t)c1 * C_HID + off];
        float4 t2 = *(const float4*)&g_hs1[(size_t)c2 * C_HID + off];
        float4 t3 = *(const float4*)&g_hs1[(size_t)c3 * C_HID + off];
        acc[0] += (t0.x + t1.x) + (t2.x + t3.x);
        acc[1] += (t0.y + t1.y) + (t2.y + t3.y);
        acc[2] += (t0.z + t1.z) + (t2.z + t3.z);
        acc[3] += (t0.w + t1.w) + (t2.w + t3.w);
    }
    for (; i < e; i++) {
        float4 t = *(const float4*)&g_hs1[(size_t)g_col[i] * C_HID + off];
        acc[0] += t.x; acc[1] += t.y; acc[2] += t.z; acc[3] += t.w;
    }
    float di = g_dinv[gw];
    __nv_bfloat16 h[4], l[4];
    #pragma unroll
    for (int v = 0; v < 4; v++) {
        float val = fmaxf(fmaf(acc[v], di, bias[off + v]), 0.f);
        split_bf16(val, h[v], l[v]);
    }
    size_t idx = (size_t)gw * C_HID + off;
    *(uint2*)&g_h2hi[idx] = *(uint2*)h;
    *(uint2*)&g_h2lo[idx] = *(uint2*)l;
}

// layer 2: out = dinv*(hs2[i] + sum_nbr) + b2   (fp32 to d_out)
__global__ void aggregate2_kernel(const float* __restrict__ bias,
                                  float* __restrict__ out) {
    int gw = (blockIdx.x * blockDim.x + threadIdx.x) >> 5;
    if (gw >= NN) return;
    int lane = threadIdx.x & 31;
    int off  = lane * 2;

    float acc[2];
    {
        float2 t = *(const float2*)&g_hs2[(size_t)gw * C_OUT + off];
        acc[0] = t.x; acc[1] = t.y;
    }
    int s = g_rowptr[gw], e = g_rowptr[gw + 1];
    int i = s;
    for (; i + 4 <= e; i += 4) {
        int c0 = g_col[i], c1 = g_col[i + 1], c2 = g_col[i + 2], c3 = g_col[i + 3];
        float2 t0 = *(const float2*)&g_hs2[(size_t)c0 * C_OUT + off];
        float2 t1 = *(const float2*)&g_hs2[(size_t)c1 * C_OUT + off];
        float2 t2 = *(const float2*)&g_hs2[(size_t)c2 * C_OUT + off];
        float2 t3 = *(const float2*)&g_hs2[(size_t)c3 * C_OUT + off];
        acc[0] += (t0.x + t1.x) + (t2.x + t3.x);
        acc[1] += (t0.y + t1.y) + (t2.y + t3.y);
    }
    for (; i < e; i++) {
        float2 t = *(const float2*)&g_hs2[(size_t)g_col[i] * C_OUT + off];
        acc[0] += t.x; acc[1] += t.y;
    }
    float di = g_dinv[gw];
    float2 r = make_float2(fmaf(acc[0], di, bias[off]),
                           fmaf(acc[1], di, bias[off + 1]));
    *(float2*)&out[(size_t)gw * C_OUT + off] = r;
}

// ---------------- launch ------------------------------------------------------
extern "C" void kernel_launch(void* const* d_in, const int* in_sizes, int n_in,
                              void* d_out, int out_size) {
    const float* x  = (const float*)d_in[0];
    const void*  ei = d_in[1];                 // int64 (or int32) [2, E]
    const float* W1 = (const float*)d_in[2];
    const float* b1 = (const float*)d_in[3];
    const float* W2 = (const float*)d_in[4];
    const float* b2 = (const float*)d_in[5];
    float* out = (float*)d_out;

    // operand prep (bf16 splits) — independent of CSR, launched first
    prep_kernel<<<(NX4 + NW1 + NW2 + 255) / 256, 256>>>(x, W1, W2);

    // CSR build
    init_kernel<<<(NN + 255) / 256, 256>>>((const long long*)ei);
    count_deg_kernel<<<(NE + 255) / 256, 256>>>(ei);
    scan_dinv_kernel<<<1, 1024>>>();
    scatter_kernel<<<(NE + 255) / 256, 256>>>(ei);

    constexpr int GB = (NN + 127) / 128;  // 235 CTAs
    // layer 1
    gemm_mma_kernel<C_HID, C_IN, 1><<<GB, 256>>>();
    aggregate1_kernel<<<(NN * 32 + 255) / 256, 256>>>(b1);
    // layer 2
    gemm_mma_kernel<C_OUT, C_HID, 2><<<GB, 256>>>();
    aggregate2_kernel<<<(NN * 32 + 255) / 256, 256>>>(b2, out);
}

// round 16
// speedup vs baseline: 1.4139x; 1.4139x over previous
#include <cuda_runtime.h>
#include <cuda_bf16.h>
#include <cstdint>

#define NN    30000
#define NE    600000
#define C_IN  256
#define C_HID 128
#define C_OUT 64

#define SCAN_BLKS  30
#define SCAN_ITEMS 1000       // SCAN_BLKS * SCAN_ITEMS = 30000 = NN

// ---------------- scratch (device globals — no allocation allowed) ----------
__device__ int   g_deg[NN];
__device__ float g_dinv[NN];
__device__ int   g_rowptr[NN + 1];
__device__ int   g_cursor[NN];
__device__ int   g_col[NE];
__device__ int   g_blk[SCAN_BLKS];
__device__ int   g_is64;
__device__ float g_hs1[(size_t)NN * C_HID];   // dinv * (X @ W1)
__device__ float g_hs2[(size_t)NN * C_OUT];   // dinv * (h2 @ W2)
// bf16 split operands for tensor-core GEMMs
__device__ __nv_bfloat16 g_xhi [(size_t)NN * C_IN];
__device__ __nv_bfloat16 g_xlo [(size_t)NN * C_IN];
__device__ __nv_bfloat16 g_h2hi[(size_t)NN * C_HID];
__device__ __nv_bfloat16 g_h2lo[(size_t)NN * C_HID];
__device__ __nv_bfloat16 g_w1thi[C_HID * C_IN];   // W1^T [n][k]
__device__ __nv_bfloat16 g_w1tlo[C_HID * C_IN];
__device__ __nv_bfloat16 g_w2thi[C_OUT * C_HID];  // W2^T [n][k]
__device__ __nv_bfloat16 g_w2tlo[C_OUT * C_HID];

// ---------------- init: zero degrees + edge dtype detection (fused) ---------
__global__ void init_kernel(const long long* __restrict__ p) {
    int i = blockIdx.x * blockDim.x + threadIdx.x;
    if (i < NN) g_deg[i] = 0;
    if (i == 0) {
        int ok = 1;
        for (int e = 0; e < 64; e++) {
            long long v = p[e];
            if (v < 0 || v >= NN) { ok = 0; break; }
        }
        g_is64 = ok;
    }
}

__global__ void count_deg_kernel(const void* __restrict__ ei) {
    int e = blockIdx.x * blockDim.x + threadIdx.x;
    if (e >= NE) return;
    int d;
    if (g_is64) d = (int)((const long long*)ei)[NE + e];
    else        d = ((const int*)ei)[NE + e];
    atomicAdd(&g_deg[d], 1);
}

// ---------------- decoupled two-phase scan (parallel + coalesced) -----------
// phase 1: per-block coalesced scan; block-local exclusive prefixes + totals
__global__ __launch_bounds__(1024)
void scan_phase1_kernel() {
    __shared__ int warp_sums[32];
    const int b = blockIdx.x, tid = threadIdx.x, lane = tid & 31, wid = tid >> 5;
    const int i = b * SCAN_ITEMS + tid;
    const int active = (tid < SCAN_ITEMS && i < NN);
    int v = active ? g_deg[i] : 0;

    int s = v;                                 // inclusive warp scan
    #pragma unroll
    for (int o = 1; o < 32; o <<= 1) {
        int t = __shfl_up_sync(0xffffffffu, s, o);
        if (lane >= o) s += t;
    }
    if (lane == 31) warp_sums[wid] = s;
    __syncthreads();
    if (wid == 0) {
        int ws = warp_sums[lane];
        #pragma unroll
        for (int o = 1; o < 32; o <<= 1) {
            int t = __shfl_up_sync(0xffffffffu, ws, o);
            if (lane >= o) ws += t;
        }
        warp_sums[lane] = ws;
    }
    __syncthreads();
    int excl = ((wid == 0) ? 0 : warp_sums[wid - 1]) + s - v;
    if (active) {
        g_rowptr[i] = excl;                    // block-local prefix (offset later)
        g_dinv[i]   = rsqrtf((float)(v + 1));  // +1 self loop
    }
    if (tid == 0) g_blk[b] = warp_sums[31];    // block total
}

// phase 2: add cross-block offsets; mirror into cursor; write grand total
__global__ __launch_bounds__(1024)
void scan_phase2_kernel() {
    __shared__ int sh_off, sh_tot;
    const int b = blockIdx.x, tid = threadIdx.x, lane = tid & 31, wid = tid >> 5;
    if (wid == 0) {
        int val = (lane < SCAN_BLKS) ? g_blk[lane] : 0;
        int s = val;                           // inclusive scan of 30 block sums
        #pragma unroll
        for (int o = 1; o < 32; o <<= 1) {
            int t = __shfl_up_sync(0xffffffffu, s, o);
            if (lane >= o) s += t;
        }
        if (lane == b)              sh_off = s - val;   // exclusive at b
        if (lane == SCAN_BLKS - 1)  sh_tot = s;         // grand total
    }
    __syncthreads();
    const int off = sh_off;
    const int i = b * SCAN_ITEMS + tid;
    if (tid < SCAN_ITEMS && i < NN) {
        int r = g_rowptr[i] + off;
        g_rowptr[i] = r;
        g_cursor[i] = r;
    }
    if (b == SCAN_BLKS - 1 && tid == 0) g_rowptr[NN] = sh_tot;
}

__global__ void scatter_kernel(const void* __restrict__ ei) {
    int e = blockIdx.x * blockDim.x + threadIdx.x;
    if (e >= NE) return;
    int s, d;
    if (g_is64) {
        s = (int)((const long long*)ei)[e];
        d = (int)((const long long*)ei)[NE + e];
    } else {
        s = ((const int*)ei)[e];
        d = ((const int*)ei)[NE + e];
    }
    int pos = atomicAdd(&g_cursor[d], 1);
    g_col[pos] = s;
}

// ---------------- bf16 split prep (x + both weights in one kernel) ----------
__device__ __forceinline__ void split_bf16(float v, __nv_bfloat16& hi,
                                           __nv_bfloat16& lo) {
    hi = __float2bfloat16(v);
    lo = __float2bfloat16(v - __bfloat162float(hi));
}

#define NX4   (NN * C_IN / 4)                     // 1,920,000 float4s of x
#define NW1   (C_HID * C_IN)
#define NW2   (C_OUT * C_HID)

__global__ void prep_kernel(const float* __restrict__ x,
                            const float* __restrict__ W1,
                            const float* __restrict__ W2) {
    int i = blockIdx.x * blockDim.x + threadIdx.x;
    if (i < NX4) {
        float4 v = ((const float4*)x)[i];
        __nv_bfloat16 h[4], l[4];
        split_bf16(v.x, h[0], l[0]); split_bf16(v.y, h[1], l[1]);
        split_bf16(v.z, h[2], l[2]); split_bf16(v.w, h[3], l[3]);
        *(uint2*)&g_xhi[(size_t)i * 4] = *(uint2*)h;
        *(uint2*)&g_xlo[(size_t)i * 4] = *(uint2*)l;
    } else {
        int j = i - NX4;
        if (j < NW1) {                         // W1^T[n][k] = W1[k][n]
            int n = j / C_IN, k = j % C_IN;
            split_bf16(W1[(size_t)k * C_HID + n], g_w1thi[j], g_w1tlo[j]);
        } else if (j < NW1 + NW2) {            // W2^T[n][k] = W2[k][n]
            int q = j - NW1;
            int n = q / C_HID, k = q % C_HID;
            split_bf16(W2[(size_t)k * C_OUT + n], g_w2thi[q], g_w2tlo[q]);
        }
    }
}

// ---------------- mma.sync helpers (baseline PTX — no sm_103a features) -----
__device__ __forceinline__ void ldm_x4(uint32_t& r0, uint32_t& r1,
                                       uint32_t& r2, uint32_t& r3,
                                       uint32_t addr) {
    asm volatile("ldmatrix.sync.aligned.m8n8.x4.shared.b16 {%0,%1,%2,%3}, [%4];"
                 : "=r"(r0), "=r"(r1), "=r"(r2), "=r"(r3) : "r"(addr));
}
__device__ __forceinline__ void mma_bf16(float* c, const uint32_t* a,
                                         const uint32_t* b) {
    asm volatile(
        "mma.sync.aligned.m16n8k16.row.col.f32.bf16.bf16.f32 "
        "{%0,%1,%2,%3}, {%4,%5,%6,%7}, {%8,%9}, {%0,%1,%2,%3};"
        : "+f"(c[0]), "+f"(c[1]), "+f"(c[2]), "+f"(c[3])
        : "r"(a[0]), "r"(a[1]), "r"(a[2]), "r"(a[3]), "r"(b[0]), "r"(b[1]));
}
__device__ __forceinline__ uint32_t smem_u32(const void* p) {
    uint32_t a;
    asm("{ .reg .u64 t; cvta.to.shared.u64 t, %1; cvt.u32.u64 %0, t; }"
        : "=r"(a) : "l"(p));
    return a;
}

// ---------------- tensor-core GEMM (HMMA) with fused dinv scale -------------
// out[row, n] = dinv[row] * sum_k A[row,k] * WT[n,k]
// 3-term bf16 split: AhiBhi + AloBhi + AhiBlo, fp32 accumulate.
// BM=128, BN = full N, BK=32, 256 threads = 8 warps (4 M x 2 N).
template<int BN, int K_TOT, int LAYER>
__global__ __launch_bounds__(256)
void gemm_mma_kernel() {
    constexpr int BM = 128, BK = 32;
    constexpr int STRIDE = BK + 8;              // bf16 units; 80B rows (conflict-free)
    constexpr int WN = BN / 2;                  // warp n-extent (64 / 32)
    constexpr int NFRAG = WN / 8;               // 8 / 4
    constexpr int MFRAG = 2;                    // 32 rows per warp

    const __nv_bfloat16 *Ahi, *Alo, *Bhi, *Blo;
    float* out;
    if constexpr (LAYER == 1) {
        Ahi = g_xhi;  Alo = g_xlo;  Bhi = g_w1thi; Blo = g_w1tlo; out = g_hs1;
    } else {
        Ahi = g_h2hi; Alo = g_h2lo; Bhi = g_w2thi; Blo = g_w2tlo; out = g_hs2;
    }

    __shared__ __nv_bfloat16 sAh[BM * STRIDE], sAl[BM * STRIDE];
    __shared__ __nv_bfloat16 sBh[BN * STRIDE], sBl[BN * STRIDE];

    const int tid   = threadIdx.x;
    const int wid   = tid >> 5, lane = tid & 31;
    const int warp_m = wid & 3, warp_n = wid >> 2;
    const int bRow  = blockIdx.x * BM;

    const uint32_t uAh = smem_u32(sAh), uAl = smem_u32(sAl);
    const uint32_t uBh = smem_u32(sBh), uBl = smem_u32(sBl);

    float acc[MFRAG][NFRAG][4];
    #pragma unroll
    for (int f = 0; f < MFRAG; f++)
        #pragma unroll
        for (int n = 0; n < NFRAG; n++)
            #pragma unroll
            for (int c = 0; c < 4; c++) acc[f][n][c] = 0.f;

    // ldmatrix per-lane row/col (same pattern for A[M][K] and B[N][K])
    const int lrow = lane & 15;
    const int lcol = (lane >> 4) << 3;

    for (int k0 = 0; k0 < K_TOT; k0 += BK) {
        // A slabs: BM x BK, vectorized uint4 (8 bf16)
        #pragma unroll
        for (int t = 0; t < BM * BK / 8 / 256; t++) {
            int u = t * 256 + tid;
            int r = u >> 2, c = u & 3;                  // 4 uint4 per row
            int grow = bRow + r;
            uint4 vh = make_uint4(0, 0, 0, 0), vl = make_uint4(0, 0, 0, 0);
            if (grow < NN) {
                size_t src = (size_t)grow * K_TOT + k0 + c * 8;
                vh = *(const uint4*)&Ahi[src];
                vl = *(const uint4*)&Alo[src];
            }
            *(uint4*)&sAh[r * STRIDE + c * 8] = vh;
            *(uint4*)&sAl[r * STRIDE + c * 8] = vl;
        }
        // B slabs: BN x BK
        #pragma unroll
        for (int t = 0; t < (BN * BK / 8 + 255) / 256; t++) {
            int u = t * 256 + tid;
            if (u < BN * BK / 8) {
                int r = u >> 2, c = u & 3;
                size_t src = (size_t)r * K_TOT + k0 + c * 8;
                *(uint4*)&sBh[r * STRIDE + c * 8] = *(const uint4*)&Bhi[src];
                *(uint4*)&sBl[r * STRIDE + c * 8] = *(const uint4*)&Blo[src];
            }
        }
        __syncthreads();

        #pragma unroll
        for (int kk = 0; kk < BK; kk += 16) {
            uint32_t ah[MFRAG][4], al[MFRAG][4];
            #pragma unroll
            for (int f = 0; f < MFRAG; f++) {
                uint32_t off = (uint32_t)((warp_m * 32 + f * 16 + lrow) * STRIDE
                                          + kk + lcol) * 2;
                ldm_x4(ah[f][0], ah[f][1], ah[f][2], ah[f][3], uAh + off);
                ldm_x4(al[f][0], al[f][1], al[f][2], al[f][3], uAl + off);
            }
            uint32_t bh[NFRAG][2], bl[NFRAG][2];
            #pragma unroll
            for (int g = 0; g < NFRAG / 2; g++) {
                uint32_t off = (uint32_t)((warp_n * WN + g * 16 + lrow) * STRIDE
                                          + kk + lcol) * 2;
                uint32_t r0, r1, r2, r3;
                ldm_x4(r0, r1, r2, r3, uBh + off);
                bh[2*g][0] = r0; bh[2*g][1] = r2;
                bh[2*g+1][0] = r1; bh[2*g+1][1] = r3;
                ldm_x4(r0, r1, r2, r3, uBl + off);
                bl[2*g][0] = r0; bl[2*g][1] = r2;
                bl[2*g+1][0] = r1; bl[2*g+1][1] = r3;
            }
            #pragma unroll
            for (int f = 0; f < MFRAG; f++)
                #pragma unroll
                for (int n = 0; n < NFRAG; n++) {
                    mma_bf16(acc[f][n], ah[f], bh[n]);   // hi*hi
                    mma_bf16(acc[f][n], al[f], bh[n]);   // lo*hi
                    mma_bf16(acc[f][n], ah[f], bl[n]);   // hi*lo
                }
        }
        __syncthreads();
    }

    // epilogue: D frag -> lane holds rows (q, q+8), cols 2*(lane%4)+{0,1}
    const int q  = lane >> 2;
    const int cc = (lane & 3) * 2;
    #pragma unroll
    for (int f = 0; f < MFRAG; f++) {
        int r0 = bRow + warp_m * 32 + f * 16 + q;
        int r1 = r0 + 8;
        float s0 = (r0 < NN) ? g_dinv[r0] : 0.f;
        float s1 = (r1 < NN) ? g_dinv[r1] : 0.f;
        #pragma unroll
        for (int n = 0; n < NFRAG; n++) {
            int col = warp_n * WN + n * 8 + cc;
            if (r0 < NN)
                *(float2*)&out[(size_t)r0 * BN + col] =
                    make_float2(acc[f][n][0] * s0, acc[f][n][1] * s0);
            if (r1 < NN)
                *(float2*)&out[(size_t)r1 * BN + col] =
                    make_float2(acc[f][n][2] * s1, acc[f][n][3] * s1);
        }
    }
}

// ---------------- CSR aggregation: one warp per node, MLP-4 unrolled --------
// layer 1: h2 = relu(dinv*(hs1[i] + sum_nbr) + b1), emitted as bf16 hi/lo split
__global__ void aggregate1_kernel(const float* __restrict__ bias) {
    int gw = (blockIdx.x * blockDim.x + threadIdx.x) >> 5;
    if (gw >= NN) return;
    int lane = threadIdx.x & 31;
    int off  = lane * 4;

    float acc[4];
    {
        float4 t = *(const float4*)&g_hs1[(size_t)gw * C_HID + off];
        acc[0] = t.x; acc[1] = t.y; acc[2] = t.z; acc[3] = t.w;
    }
    int s = g_rowptr[gw], e = g_rowptr[gw + 1];
    int i = s;
    for (; i + 4 <= e; i += 4) {               // MLP-4: batch cols, then rows
        int c0 = g_col[i], c1 = g_col[i + 1], c2 = g_col[i + 2], c3 = g_col[i + 3];
        float4 t0 = *(const float4*)&g_hs1[(size_t)c0 * C_HID + off];
        float4 t1 = *(const float4*)&g_hs1[(size_t)c1 * C_HID + off];
        float4 t2 = *(const float4*)&g_hs1[(size_t)c2 * C_HID + off];
        float4 t3 = *(const float4*)&g_hs1[(size_t)c3 * C_HID + off];
        acc[0] += (t0.x + t1.x) + (t2.x + t3.x);
        acc[1] += (t0.y + t1.y) + (t2.y + t3.y);
        acc[2] += (t0.z + t1.z) + (t2.z + t3.z);
        acc[3] += (t0.w + t1.w) + (t2.w + t3.w);
    }
    for (; i < e; i++) {
        float4 t = *(const float4*)&g_hs1[(size_t)g_col[i] * C_HID + off];
        acc[0] += t.x; acc[1] += t.y; acc[2] += t.z; acc[3] += t.w;
    }
    float di = g_dinv[gw];
    __nv_bfloat16 h[4], l[4];
    #pragma unroll
    for (int v = 0; v < 4; v++) {
        float val = fmaxf(fmaf(acc[v], di, bias[off + v]), 0.f);
        split_bf16(val, h[v], l[v]);
    }
    size_t idx = (size_t)gw * C_HID + off;
    *(uint2*)&g_h2hi[idx] = *(uint2*)h;
    *(uint2*)&g_h2lo[idx] = *(uint2*)l;
}

// layer 2: out = dinv*(hs2[i] + sum_nbr) + b2   (fp32 to d_out)
__global__ void aggregate2_kernel(const float* __restrict__ bias,
                                  float* __restrict__ out) {
    int gw = (blockIdx.x * blockDim.x + threadIdx.x) >> 5;
    if (gw >= NN) return;
    int lane = threadIdx.x & 31;
    int off  = lane * 2;

    float acc[2];
    {
        float2 t = *(const float2*)&g_hs2[(size_t)gw * C_OUT + off];
        acc[0] = t.x; acc[1] = t.y;
    }
    int s = g_rowptr[gw], e = g_rowptr[gw + 1];
    int i = s;
    for (; i + 4 <= e; i += 4) {
        int c0 = g_col[i], c1 = g_col[i + 1], c2 = g_col[i + 2], c3 = g_col[i + 3];
        float2 t0 = *(const float2*)&g_hs2[(size_t)c0 * C_OUT + off];
        float2 t1 = *(const float2*)&g_hs2[(size_t)c1 * C_OUT + off];
        float2 t2 = *(const float2*)&g_hs2[(size_t)c2 * C_OUT + off];
        float2 t3 = *(const float2*)&g_hs2[(size_t)c3 * C_OUT + off];
        acc[0] += (t0.x + t1.x) + (t2.x + t3.x);
        acc[1] += (t0.y + t1.y) + (t2.y + t3.y);
    }
    for (; i < e; i++) {
        float2 t = *(const float2*)&g_hs2[(size_t)g_col[i] * C_OUT + off];
        acc[0] += t.x; acc[1] += t.y;
    }
    float di = g_dinv[gw];
    float2 r = make_float2(fmaf(acc[0], di, bias[off]),
                           fmaf(acc[1], di, bias[off + 1]));
    *(float2*)&out[(size_t)gw * C_OUT + off] = r;
}

// ---------------- launch ------------------------------------------------------
extern "C" void kernel_launch(void* const* d_in, const int* in_sizes, int n_in,
                              void* d_out, int out_size) {
    const float* x  = (const float*)d_in[0];
    const void*  ei = d_in[1];                 // int64 (or int32) [2, E]
    const float* W1 = (const float*)d_in[2];
    const float* b1 = (const float*)d_in[3];
    const float* W2 = (const float*)d_in[4];
    const float* b2 = (const float*)d_in[5];
    float* out = (float*)d_out;

    // operand prep (bf16 splits) — independent of CSR, launched first
    prep_kernel<<<(NX4 + NW1 + NW2 + 255) / 256, 256>>>(x, W1, W2);

    // CSR build
    init_kernel<<<(NN + 255) / 256, 256>>>((const long long*)ei);
    count_deg_kernel<<<(NE + 255) / 256, 256>>>(ei);
    scan_phase1_kernel<<<SCAN_BLKS, 1024>>>();
    scan_phase2_kernel<<<SCAN_BLKS, 1024>>>();
    scatter_kernel<<<(NE + 255) / 256, 256>>>(ei);

    constexpr int GB = (NN + 127) / 128;  // 235 CTAs
    // layer 1
    gemm_mma_kernel<C_HID, C_IN, 1><<<GB, 256>>>();
    aggregate1_kernel<<<(NN * 32 + 255) / 256, 256>>>(b1);
    // layer 2
    gemm_mma_kernel<C_OUT, C_HID, 2><<<GB, 256>>>();
    aggregate2_kernel<<<(NN * 32 + 255) / 256, 256>>>(b2, out);
}

// round 17
// speedup vs baseline: 1.5195x; 1.0747x over previous
#include <cuda_runtime.h>
#include <cuda_bf16.h>
#include <cstdint>

#define NN    30000
#define NE    600000
#define C_IN  256
#define C_HID 128
#define C_OUT 64

#define SCAN_BLKS  30
#define SCAN_ITEMS 1000       // SCAN_BLKS * SCAN_ITEMS = 30000 = NN

// ---------------- scratch (device globals — no allocation allowed) ----------
__device__ int   g_deg[NN];
__device__ float g_dinv[NN];
__device__ int   g_rowptr[NN + 1];
__device__ int   g_cursor[NN];
__device__ int   g_col[NE];
__device__ int   g_blk[SCAN_BLKS];
__device__ int   g_is64;
__device__ float g_hs1[(size_t)NN * C_HID];   // X @ W1          (unscaled)
__device__ float g_hs2[(size_t)NN * C_OUT];   // h2 @ W2         (unscaled)
// bf16 split operands for tensor-core GEMMs
__device__ __nv_bfloat16 g_xhi [(size_t)NN * C_IN];
__device__ __nv_bfloat16 g_xlo [(size_t)NN * C_IN];
__device__ __nv_bfloat16 g_h2hi[(size_t)NN * C_HID];
__device__ __nv_bfloat16 g_h2lo[(size_t)NN * C_HID];
__device__ __nv_bfloat16 g_w1thi[C_HID * C_IN];   // W1^T [n][k]
__device__ __nv_bfloat16 g_w1tlo[C_HID * C_IN];
__device__ __nv_bfloat16 g_w2thi[C_OUT * C_HID];  // W2^T [n][k]
__device__ __nv_bfloat16 g_w2tlo[C_OUT * C_HID];

// ---------------- init: zero degrees + edge dtype detection (fused) ---------
__global__ void init_kernel(const long long* __restrict__ p) {
    int i = blockIdx.x * blockDim.x + threadIdx.x;
    if (i < NN) g_deg[i] = 0;
    if (i == 0) {
        int ok = 1;
        for (int e = 0; e < 64; e++) {
            long long v = p[e];
            if (v < 0 || v >= NN) { ok = 0; break; }
        }
        g_is64 = ok;
    }
}

__global__ void count_deg_kernel(const void* __restrict__ ei) {
    int e = blockIdx.x * blockDim.x + threadIdx.x;
    if (e >= NE) return;
    int d;
    if (g_is64) d = (int)((const long long*)ei)[NE + e];
    else        d = ((const int*)ei)[NE + e];
    atomicAdd(&g_deg[d], 1);
}

// ---------------- decoupled two-phase scan (parallel + coalesced) -----------
__global__ __launch_bounds__(1024)
void scan_phase1_kernel() {
    __shared__ int warp_sums[32];
    const int b = blockIdx.x, tid = threadIdx.x, lane = tid & 31, wid = tid >> 5;
    const int i = b * SCAN_ITEMS + tid;
    const int active = (tid < SCAN_ITEMS && i < NN);
    int v = active ? g_deg[i] : 0;

    int s = v;                                 // inclusive warp scan
    #pragma unroll
    for (int o = 1; o < 32; o <<= 1) {
        int t = __shfl_up_sync(0xffffffffu, s, o);
        if (lane >= o) s += t;
    }
    if (lane == 31) warp_sums[wid] = s;
    __syncthreads();
    if (wid == 0) {
        int ws = warp_sums[lane];
        #pragma unroll
        for (int o = 1; o < 32; o <<= 1) {
            int t = __shfl_up_sync(0xffffffffu, ws, o);
            if (lane >= o) ws += t;
        }
        warp_sums[lane] = ws;
    }
    __syncthreads();
    int excl = ((wid == 0) ? 0 : warp_sums[wid - 1]) + s - v;
    if (active) {
        g_rowptr[i] = excl;                    // block-local prefix (offset later)
        g_dinv[i]   = rsqrtf((float)(v + 1));  // +1 self loop
    }
    if (tid == 0) g_blk[b] = warp_sums[31];    // block total
}

__global__ __launch_bounds__(1024)
void scan_phase2_kernel() {
    __shared__ int sh_off, sh_tot;
    const int b = blockIdx.x, tid = threadIdx.x, lane = tid & 31, wid = tid >> 5;
    if (wid == 0) {
        int val = (lane < SCAN_BLKS) ? g_blk[lane] : 0;
        int s = val;                           // inclusive scan of 30 block sums
        #pragma unroll
        for (int o = 1; o < 32; o <<= 1) {
            int t = __shfl_up_sync(0xffffffffu, s, o);
            if (lane >= o) s += t;
        }
        if (lane == b)              sh_off = s - val;   // exclusive at b
        if (lane == SCAN_BLKS - 1)  sh_tot = s;         // grand total
    }
    __syncthreads();
    const int off = sh_off;
    const int i = b * SCAN_ITEMS + tid;
    if (tid < SCAN_ITEMS && i < NN) {
        int r = g_rowptr[i] + off;
        g_rowptr[i] = r;
        g_cursor[i] = r;
    }
    if (b == SCAN_BLKS - 1 && tid == 0) g_rowptr[NN] = sh_tot;
}

__global__ void scatter_kernel(const void* __restrict__ ei) {
    int e = blockIdx.x * blockDim.x + threadIdx.x;
    if (e >= NE) return;
    int s, d;
    if (g_is64) {
        s = (int)((const long long*)ei)[e];
        d = (int)((const long long*)ei)[NE + e];
    } else {
        s = ((const int*)ei)[e];
        d = ((const int*)ei)[NE + e];
    }
    int pos = atomicAdd(&g_cursor[d], 1);
    g_col[pos] = s;
}

// ---------------- bf16 split prep (x + both weights in one kernel) ----------
__device__ __forceinline__ void split_bf16(float v, __nv_bfloat16& hi,
                                           __nv_bfloat16& lo) {
    hi = __float2bfloat16(v);
    lo = __float2bfloat16(v - __bfloat162float(hi));
}

#define NX4   (NN * C_IN / 4)                     // 1,920,000 float4s of x
#define NW1   (C_HID * C_IN)
#define NW2   (C_OUT * C_HID)

__global__ void prep_kernel(const float* __restrict__ x,
                            const float* __restrict__ W1,
                            const float* __restrict__ W2) {
    int i = blockIdx.x * blockDim.x + threadIdx.x;
    if (i < NX4) {
        float4 v = ((const float4*)x)[i];
        __nv_bfloat16 h[4], l[4];
        split_bf16(v.x, h[0], l[0]); split_bf16(v.y, h[1], l[1]);
        split_bf16(v.z, h[2], l[2]); split_bf16(v.w, h[3], l[3]);
        *(uint2*)&g_xhi[(size_t)i * 4] = *(uint2*)h;
        *(uint2*)&g_xlo[(size_t)i * 4] = *(uint2*)l;
    } else {
        int j = i - NX4;
        if (j < NW1) {                         // W1^T[n][k] = W1[k][n]
            int n = j / C_IN, k = j % C_IN;
            split_bf16(W1[(size_t)k * C_HID + n], g_w1thi[j], g_w1tlo[j]);
        } else if (j < NW1 + NW2) {            // W2^T[n][k] = W2[k][n]
            int q = j - NW1;
            int n = q / C_HID, k = q % C_HID;
            split_bf16(W2[(size_t)k * C_OUT + n], g_w2thi[q], g_w2tlo[q]);
        }
    }
}

// ---------------- mma.sync helpers (baseline PTX — no sm_103a features) -----
__device__ __forceinline__ void ldm_x4(uint32_t& r0, uint32_t& r1,
                                       uint32_t& r2, uint32_t& r3,
                                       uint32_t addr) {
    asm volatile("ldmatrix.sync.aligned.m8n8.x4.shared.b16 {%0,%1,%2,%3}, [%4];"
                 : "=r"(r0), "=r"(r1), "=r"(r2), "=r"(r3) : "r"(addr));
}
__device__ __forceinline__ void mma_bf16(float* c, const uint32_t* a,
                                         const uint32_t* b) {
    asm volatile(
        "mma.sync.aligned.m16n8k16.row.col.f32.bf16.bf16.f32 "
        "{%0,%1,%2,%3}, {%4,%5,%6,%7}, {%8,%9}, {%0,%1,%2,%3};"
        : "+f"(c[0]), "+f"(c[1]), "+f"(c[2]), "+f"(c[3])
        : "r"(a[0]), "r"(a[1]), "r"(a[2]), "r"(a[3]), "r"(b[0]), "r"(b[1]));
}
__device__ __forceinline__ uint32_t smem_u32(const void* p) {
    uint32_t a;
    asm("{ .reg .u64 t; cvta.to.shared.u64 t, %1; cvt.u32.u64 %0, t; }"
        : "=r"(a) : "l"(p));
    return a;
}

// ---------------- tensor-core GEMM (HMMA), raw output (no dinv) -------------
// out[row, n] = sum_k A[row,k] * WT[n,k]
// 3-term bf16 split: AhiBhi + AloBhi + AhiBlo, fp32 accumulate.
// BM=128, BN = full N, BK=32, 256 threads = 8 warps (4 M x 2 N).
template<int BN, int K_TOT, int LAYER>
__global__ __launch_bounds__(256)
void gemm_mma_kernel() {
    constexpr int BM = 128, BK = 32;
    constexpr int STRIDE = BK + 8;              // bf16 units; 80B rows (conflict-free)
    constexpr int WN = BN / 2;                  // warp n-extent (64 / 32)
    constexpr int NFRAG = WN / 8;               // 8 / 4
    constexpr int MFRAG = 2;                    // 32 rows per warp

    const __nv_bfloat16 *Ahi, *Alo, *Bhi, *Blo;
    float* out;
    if constexpr (LAYER == 1) {
        Ahi = g_xhi;  Alo = g_xlo;  Bhi = g_w1thi; Blo = g_w1tlo; out = g_hs1;
    } else {
        Ahi = g_h2hi; Alo = g_h2lo; Bhi = g_w2thi; Blo = g_w2tlo; out = g_hs2;
    }

    __shared__ __nv_bfloat16 sAh[BM * STRIDE], sAl[BM * STRIDE];
    __shared__ __nv_bfloat16 sBh[BN * STRIDE], sBl[BN * STRIDE];

    const int tid   = threadIdx.x;
    const int wid   = tid >> 5, lane = tid & 31;
    const int warp_m = wid & 3, warp_n = wid >> 2;
    const int bRow  = blockIdx.x * BM;

    const uint32_t uAh = smem_u32(sAh), uAl = smem_u32(sAl);
    const uint32_t uBh = smem_u32(sBh), uBl = smem_u32(sBl);

    float acc[MFRAG][NFRAG][4];
    #pragma unroll
    for (int f = 0; f < MFRAG; f++)
        #pragma unroll
        for (int n = 0; n < NFRAG; n++)
            #pragma unroll
            for (int c = 0; c < 4; c++) acc[f][n][c] = 0.f;

    const int lrow = lane & 15;
    const int lcol = (lane >> 4) << 3;

    for (int k0 = 0; k0 < K_TOT; k0 += BK) {
        #pragma unroll
        for (int t = 0; t < BM * BK / 8 / 256; t++) {
            int u = t * 256 + tid;
            int r = u >> 2, c = u & 3;                  // 4 uint4 per row
            int grow = bRow + r;
            uint4 vh = make_uint4(0, 0, 0, 0), vl = make_uint4(0, 0, 0, 0);
            if (grow < NN) {
                size_t src = (size_t)grow * K_TOT + k0 + c * 8;
                vh = *(const uint4*)&Ahi[src];
                vl = *(const uint4*)&Alo[src];
            }
            *(uint4*)&sAh[r * STRIDE + c * 8] = vh;
            *(uint4*)&sAl[r * STRIDE + c * 8] = vl;
        }
        #pragma unroll
        for (int t = 0; t < (BN * BK / 8 + 255) / 256; t++) {
            int u = t * 256 + tid;
            if (u < BN * BK / 8) {
                int r = u >> 2, c = u & 3;
                size_t src = (size_t)r * K_TOT + k0 + c * 8;
                *(uint4*)&sBh[r * STRIDE + c * 8] = *(const uint4*)&Bhi[src];
                *(uint4*)&sBl[r * STRIDE + c * 8] = *(const uint4*)&Blo[src];
            }
        }
        __syncthreads();

        #pragma unroll
        for (int kk = 0; kk < BK; kk += 16) {
            uint32_t ah[MFRAG][4], al[MFRAG][4];
            #pragma unroll
            for (int f = 0; f < MFRAG; f++) {
                uint32_t off = (uint32_t)((warp_m * 32 + f * 16 + lrow) * STRIDE
                                          + kk + lcol) * 2;
                ldm_x4(ah[f][0], ah[f][1], ah[f][2], ah[f][3], uAh + off);
                ldm_x4(al[f][0], al[f][1], al[f][2], al[f][3], uAl + off);
            }
            uint32_t bh[NFRAG][2], bl[NFRAG][2];
            #pragma unroll
            for (int g = 0; g < NFRAG / 2; g++) {
                uint32_t off = (uint32_t)((warp_n * WN + g * 16 + lrow) * STRIDE
                                          + kk + lcol) * 2;
                uint32_t r0, r1, r2, r3;
                ldm_x4(r0, r1, r2, r3, uBh + off);
                bh[2*g][0] = r0; bh[2*g][1] = r2;
                bh[2*g+1][0] = r1; bh[2*g+1][1] = r3;
                ldm_x4(r0, r1, r2, r3, uBl + off);
                bl[2*g][0] = r0; bl[2*g][1] = r2;
                bl[2*g+1][0] = r1; bl[2*g+1][1] = r3;
            }
            #pragma unroll
            for (int f = 0; f < MFRAG; f++)
                #pragma unroll
                for (int n = 0; n < NFRAG; n++) {
                    mma_bf16(acc[f][n], ah[f], bh[n]);   // hi*hi
                    mma_bf16(acc[f][n], al[f], bh[n]);   // lo*hi
                    mma_bf16(acc[f][n], ah[f], bl[n]);   // hi*lo
                }
        }
        __syncthreads();
    }

    // epilogue (raw store; dinv applied in aggregation)
    const int q  = lane >> 2;
    const int cc = (lane & 3) * 2;
    #pragma unroll
    for (int f = 0; f < MFRAG; f++) {
        int r0 = bRow + warp_m * 32 + f * 16 + q;
        int r1 = r0 + 8;
        #pragma unroll
        for (int n = 0; n < NFRAG; n++) {
            int col = warp_n * WN + n * 8 + cc;
            if (r0 < NN)
                *(float2*)&out[(size_t)r0 * BN + col] =
                    make_float2(acc[f][n][0], acc[f][n][1]);
            if (r1 < NN)
                *(float2*)&out[(size_t)r1 * BN + col] =
                    make_float2(acc[f][n][2], acc[f][n][3]);
        }
    }
}

// ---------------- CSR aggregation: one warp per node, MLP-4 unrolled --------
// out[d] = dinv[d] * ( dinv[d]*hs[d] + sum_s dinv[s]*hs[s] )  (+bias, relu)
__global__ void aggregate1_kernel(const float* __restrict__ bias) {
    int gw = (blockIdx.x * blockDim.x + threadIdx.x) >> 5;
    if (gw >= NN) return;
    int lane = threadIdx.x & 31;
    int off  = lane * 4;

    float di = g_dinv[gw];
    float acc[4];
    {
        float4 t = *(const float4*)&g_hs1[(size_t)gw * C_HID + off];
        acc[0] = t.x * di; acc[1] = t.y * di; acc[2] = t.z * di; acc[3] = t.w * di;
    }
    int s = g_rowptr[gw], e = g_rowptr[gw + 1];
    int i = s;
    for (; i + 4 <= e; i += 4) {               // MLP-4: batch cols, then rows
        int c0 = g_col[i], c1 = g_col[i + 1], c2 = g_col[i + 2], c3 = g_col[i + 3];
        float s0 = g_dinv[c0], s1 = g_dinv[c1], s2 = g_dinv[c2], s3 = g_dinv[c3];
        float4 t0 = *(const float4*)&g_hs1[(size_t)c0 * C_HID + off];
        float4 t1 = *(const float4*)&g_hs1[(size_t)c1 * C_HID + off];
        float4 t2 = *(const float4*)&g_hs1[(size_t)c2 * C_HID + off];
        float4 t3 = *(const float4*)&g_hs1[(size_t)c3 * C_HID + off];
        acc[0] = fmaf(t0.x, s0, fmaf(t1.x, s1, fmaf(t2.x, s2, fmaf(t3.x, s3, acc[0]))));
        acc[1] = fmaf(t0.y, s0, fmaf(t1.y, s1, fmaf(t2.y, s2, fmaf(t3.y, s3, acc[1]))));
        acc[2] = fmaf(t0.z, s0, fmaf(t1.z, s1, fmaf(t2.z, s2, fmaf(t3.z, s3, acc[2]))));
        acc[3] = fmaf(t0.w, s0, fmaf(t1.w, s1, fmaf(t2.w, s2, fmaf(t3.w, s3, acc[3]))));
    }
    for (; i < e; i++) {
        int c = g_col[i];
        float sc = g_dinv[c];
        float4 t = *(const float4*)&g_hs1[(size_t)c * C_HID + off];
        acc[0] = fmaf(t.x, sc, acc[0]); acc[1] = fmaf(t.y, sc, acc[1]);
        acc[2] = fmaf(t.z, sc, acc[2]); acc[3] = fmaf(t.w, sc, acc[3]);
    }
    __nv_bfloat16 h[4], l[4];
    #pragma unroll
    for (int v = 0; v < 4; v++) {
        float val = fmaxf(fmaf(acc[v], di, bias[off + v]), 0.f);
        split_bf16(val, h[v], l[v]);
    }
    size_t idx = (size_t)gw * C_HID + off;
    *(uint2*)&g_h2hi[idx] = *(uint2*)h;
    *(uint2*)&g_h2lo[idx] = *(uint2*)l;
}

__global__ void aggregate2_kernel(const float* __restrict__ bias,
                                  float* __restrict__ out) {
    int gw = (blockIdx.x * blockDim.x + threadIdx.x) >> 5;
    if (gw >= NN) return;
    int lane = threadIdx.x & 31;
    int off  = lane * 2;

    float di = g_dinv[gw];
    float acc[2];
    {
        float2 t = *(const float2*)&g_hs2[(size_t)gw * C_OUT + off];
        acc[0] = t.x * di; acc[1] = t.y * di;
    }
    int s = g_rowptr[gw], e = g_rowptr[gw + 1];
    int i = s;
    for (; i + 4 <= e; i += 4) {
        int c0 = g_col[i], c1 = g_col[i + 1], c2 = g_col[i + 2], c3 = g_col[i + 3];
        float s0 = g_dinv[c0], s1 = g_dinv[c1], s2 = g_dinv[c2], s3 = g_dinv[c3];
        float2 t0 = *(const float2*)&g_hs2[(size_t)c0 * C_OUT + off];
        float2 t1 = *(const float2*)&g_hs2[(size_t)c1 * C_OUT + off];
        float2 t2 = *(const float2*)&g_hs2[(size_t)c2 * C_OUT + off];
        float2 t3 = *(const float2*)&g_hs2[(size_t)c3 * C_OUT + off];
        acc[0] = fmaf(t0.x, s0, fmaf(t1.x, s1, fmaf(t2.x, s2, fmaf(t3.x, s3, acc[0]))));
        acc[1] = fmaf(t0.y, s0, fmaf(t1.y, s1, fmaf(t2.y, s2, fmaf(t3.y, s3, acc[1]))));
    }
    for (; i < e; i++) {
        int c = g_col[i];
        float sc = g_dinv[c];
        float2 t = *(const float2*)&g_hs2[(size_t)c * C_OUT + off];
        acc[0] = fmaf(t.x, sc, acc[0]); acc[1] = fmaf(t.y, sc, acc[1]);
    }
    float2 r = make_float2(fmaf(acc[0], di, bias[off]),
                           fmaf(acc[1], di, bias[off + 1]));
    *(float2*)&out[(size_t)gw * C_OUT + off] = r;
}

// ---------------- launch: stream-forked capture graph ------------------------
extern "C" void kernel_launch(void* const* d_in, const int* in_sizes, int n_in,
                              void* d_out, int out_size) {
    const float* x  = (const float*)d_in[0];
    const void*  ei = d_in[1];                 // int64 (or int32) [2, E]
    const float* W1 = (const float*)d_in[2];
    const float* b1 = (const float*)d_in[3];
    const float* W2 = (const float*)d_in[4];
    const float* b2 = (const float*)d_in[5];
    float* out = (float*)d_out;

    // fork: CSR chain on side stream, dense chain on main (default) stream
    cudaStream_t s2;
    cudaStreamCreateWithFlags(&s2, cudaStreamNonBlocking);
    cudaEvent_t evFork, evCsr;
    cudaEventCreateWithFlags(&evFork, cudaEventDisableTiming);
    cudaEventCreateWithFlags(&evCsr,  cudaEventDisableTiming);

    cudaEventRecord(evFork, 0);
    cudaStreamWaitEvent(s2, evFork, 0);

    // side stream: CSR build (independent of dense path)
    init_kernel<<<(NN + 255) / 256, 256, 0, s2>>>((const long long*)ei);
    count_deg_kernel<<<(NE + 255) / 256, 256, 0, s2>>>(ei);
    scan_phase1_kernel<<<SCAN_BLKS, 1024, 0, s2>>>();
    scan_phase2_kernel<<<SCAN_BLKS, 1024, 0, s2>>>();
    scatter_kernel<<<(NE + 255) / 256, 256, 0, s2>>>(ei);
    cudaEventRecord(evCsr, s2);

    // main stream: bf16 prep + GEMM1 (no dinv dependency anymore)
    prep_kernel<<<(NX4 + NW1 + NW2 + 255) / 256, 256>>>(x, W1, W2);
    constexpr int GB = (NN + 127) / 128;  // 235 CTAs
    gemm_mma_kernel<C_HID, C_IN, 1><<<GB, 256>>>();

    // join: aggregation needs CSR + dinv + GEMM1
    cudaStreamWaitEvent(0, evCsr, 0);
    aggregate1_kernel<<<(NN * 32 + 255) / 256, 256>>>(b1);
    gemm_mma_kernel<C_OUT, C_HID, 2><<<GB, 256>>>();
    aggregate2_kernel<<<(NN * 32 + 255) / 256, 256>>>(b2, out);

    cudaEventDestroy(evFork);
    cudaEventDestroy(evCsr);
    cudaStreamDestroy(s2);
}